// round 12
// baseline (speedup 1.0000x reference)
#include <cuda_runtime.h>
#include <cuda_bf16.h>
#include <cstdint>

// Problem constants
#define B_   2
#define T_   2048
#define D_   1024
#define H_   16
#define HD_  64
#define M_TOT (B_ * T_)          // 4096 rows

// Scratch (alloc-free rule: __device__ globals). All tf32 bit patterns.
__device__ __align__(16) uint32_t g_x_tf [(size_t)M_TOT * D_];
__device__ __align__(16) uint32_t g_wq_tf[(size_t)3 * D_ * D_];
__device__ __align__(16) uint32_t g_wo_tf[(size_t)D_ * D_];
__device__ __align__(16) uint32_t g_qkv  [(size_t)M_TOT * 3 * D_];
__device__ __align__(16) uint32_t g_att  [(size_t)M_TOT * D_];

// ---------------------------------------------------------------------------
// helpers
// ---------------------------------------------------------------------------
__device__ __forceinline__ uint32_t f2tf(float x) {
    uint32_t u; asm("cvt.rna.tf32.f32 %0, %1;" : "=r"(u) : "f"(x)); return u;
}
__device__ __forceinline__ void mma_tf32(float* c, const uint32_t* a,
                                         uint32_t b0, uint32_t b1) {
    asm volatile(
        "mma.sync.aligned.m16n8k8.row.col.f32.tf32.tf32.f32 "
        "{%0,%1,%2,%3}, {%4,%5,%6,%7}, {%8,%9}, {%0,%1,%2,%3};\n"
        : "+f"(c[0]), "+f"(c[1]), "+f"(c[2]), "+f"(c[3])
        : "r"(a[0]), "r"(a[1]), "r"(a[2]), "r"(a[3]), "r"(b0), "r"(b1));
}
#define CP_ASYNC16(dst, src) \
    asm volatile("cp.async.cg.shared.global [%0], [%1], 16;\n" :: "r"(dst), "l"(src))
#define CP_COMMIT() asm volatile("cp.async.commit_group;\n" ::)
#define CP_WAIT(n)  asm volatile("cp.async.wait_group %0;\n" :: "n"(n))

__device__ __forceinline__ uint32_t s2u(const void* p) {
    return (uint32_t)__cvta_generic_to_shared(p);
}

// ---------------------------------------------------------------------------
// elementwise fp32 -> tf32 bits
// ---------------------------------------------------------------------------
__global__ void __launch_bounds__(256) conv_tf32_kernel(
    const float* __restrict__ in, uint32_t* __restrict__ out, int n)
{
    int i = (blockIdx.x * 256 + threadIdx.x) * 4;
    if (i < n) {
        float4 v = *(const float4*)(in + i);
        uint4 o = make_uint4(f2tf(v.x), f2tf(v.y), f2tf(v.z), f2tf(v.w));
        *(uint4*)(out + i) = o;
    }
}

// ---------------------------------------------------------------------------
// TF32 mma.sync GEMM v3 (cutlass sm80-style shape): C[M,N] = A[M,K] @ W[N,K]^T
// Block 128x128, 4 warps (2x2), warp tile 64x64, BK=16,
// 3-stage cp.async ring with ONE barrier per iteration:
//   iter kt: wait(load kt) ; barrier ; issue load(kt+2) ; compute(kt)
// The barrier proves all warps finished compute(kt-1), whose stage
// (kt-1)%3 == (kt+2)%3 is what load(kt+2) overwrites.
// Smem pitch 20 words: fragment rows (g*20+t) mod 32 all distinct.
// conv_out: 1 -> store tf32 bits; 0 -> store fp32.
// ---------------------------------------------------------------------------
#define GBM 128
#define GBN 128
#define GBK 16
#define GP  20                        // row pitch (words)
#define GAW (GBM * GP)                // A stage words = 2560
#define GSW (2 * GAW)                 // stage words   = 5120
#define GEMM_SMEM (3 * GSW * 4)       // 61440 bytes

__device__ __forceinline__ void gemm_load_stage(
    const uint32_t* __restrict__ A, const uint32_t* __restrict__ W,
    uint32_t sbase_b, int m0, int n0, int K, int kt, int tid)
{
    // 128 threads: thread tid loads A row tid and W row tid (16 words each)
    const uint32_t* gA = A + (size_t)(m0 + tid) * K + kt * GBK;
    const uint32_t* gW = W + (size_t)(n0 + tid) * K + kt * GBK;
    const uint32_t aD = sbase_b + (uint32_t)(tid * GP) * 4;
    const uint32_t bD = aD + GAW * 4;
    #pragma unroll
    for (int j = 0; j < 4; j++) {
        CP_ASYNC16(aD + j * 16, gA + j * 4);
        CP_ASYNC16(bD + j * 16, gW + j * 4);
    }
}

__global__ void __launch_bounds__(128) gemm_tt32(
    const uint32_t* __restrict__ A, const uint32_t* __restrict__ W,
    void* __restrict__ Cout, int M, int N, int K, int conv_out)
{
    extern __shared__ uint32_t dsm[];

    const int tid  = threadIdx.x;
    const int warp = tid >> 5;
    const int lane = tid & 31;
    const int g = lane >> 2;
    const int t = lane & 3;
    const int wm = (warp >> 1) * 64;     // 0, 64
    const int wn = (warp & 1) * 64;      // 0, 64

    const int m0 = blockIdx.y * GBM;
    const int n0 = blockIdx.x * GBN;
    const uint32_t sb = s2u(dsm);

    float acc[4][8][4] = {};
    const int KT = K / GBK;              // 64

    // prologue: stages 0,1 in flight
    gemm_load_stage(A, W, sb + 0 * GSW * 4, m0, n0, K, 0, tid); CP_COMMIT();
    gemm_load_stage(A, W, sb + 1 * GSW * 4, m0, n0, K, 1, tid); CP_COMMIT();

    for (int kt = 0; kt < KT; kt++) {
        const int s = kt % 3;
        if (kt + 1 < KT) { CP_WAIT(1); } else { CP_WAIT(0); }
        __syncthreads();
        if (kt + 2 < KT) {
            gemm_load_stage(A, W, sb + ((kt + 2) % 3) * GSW * 4,
                            m0, n0, K, kt + 2, tid);
            CP_COMMIT();
        }

        const uint32_t* As = dsm + s * GSW;
        const uint32_t* Bs = As + GAW;
        #pragma unroll
        for (int ks = 0; ks < 2; ks++) {
            const int k = ks * 8;
            uint32_t af[4][4];
            #pragma unroll
            for (int mi = 0; mi < 4; mi++) {
                const int r = wm + mi * 16 + g;
                af[mi][0] = As[r * GP + k + t];
                af[mi][1] = As[(r + 8) * GP + k + t];
                af[mi][2] = As[r * GP + k + t + 4];
                af[mi][3] = As[(r + 8) * GP + k + t + 4];
            }
            uint32_t bf[8][2];
            #pragma unroll
            for (int ni = 0; ni < 8; ni++) {
                const int rb = wn + ni * 8 + g;
                bf[ni][0] = Bs[rb * GP + k + t];
                bf[ni][1] = Bs[rb * GP + k + t + 4];
            }
            #pragma unroll
            for (int ni = 0; ni < 8; ni++)
                #pragma unroll
                for (int mi = 0; mi < 4; mi++)
                    mma_tf32(acc[mi][ni], af[mi], bf[ni][0], bf[ni][1]);
        }
    }

    // epilogue
    if (conv_out) {
        uint32_t* C = (uint32_t*)Cout;
        #pragma unroll
        for (int mi = 0; mi < 4; mi++) {
            const int r1 = m0 + wm + mi * 16 + g;
            const int r2 = r1 + 8;
            #pragma unroll
            for (int ni = 0; ni < 8; ni++) {
                const int c = n0 + wn + ni * 8 + 2 * t;
                *(uint2*)&C[(size_t)r1 * N + c] =
                    make_uint2(f2tf(acc[mi][ni][0]), f2tf(acc[mi][ni][1]));
                *(uint2*)&C[(size_t)r2 * N + c] =
                    make_uint2(f2tf(acc[mi][ni][2]), f2tf(acc[mi][ni][3]));
            }
        }
    } else {
        float* C = (float*)Cout;
        #pragma unroll
        for (int mi = 0; mi < 4; mi++) {
            const int r1 = m0 + wm + mi * 16 + g;
            const int r2 = r1 + 8;
            #pragma unroll
            for (int ni = 0; ni < 8; ni++) {
                const int c = n0 + wn + ni * 8 + 2 * t;
                *(float2*)&C[(size_t)r1 * N + c] =
                    make_float2(acc[mi][ni][0], acc[mi][ni][1]);
                *(float2*)&C[(size_t)r2 * N + c] =
                    make_float2(acc[mi][ni][2], acc[mi][ni][3]);
            }
        }
    }
}

// ---------------------------------------------------------------------------
// Tensor-core flash attention (causal), tf32 inputs — R9 version (known-good,
// fastest measured). Grid: (T/128, H, B), 256 threads = 8 warps.
// ---------------------------------------------------------------------------
#define AQ 128

__global__ void __launch_bounds__(256) attn_tc_kernel(
    const uint32_t* __restrict__ qkv, uint32_t* __restrict__ out)
{
    __shared__ uint32_t Ks[64][68];
    __shared__ uint32_t VsT[64][68];

    const int qt  = gridDim.x - 1 - blockIdx.x;  // heavy first
    const int h   = blockIdx.y;
    const int b   = blockIdx.z;
    const int tid = threadIdx.x;
    const int warp = tid >> 5;
    const int lane = tid & 31;
    const int g = lane >> 2;
    const int t = lane & 3;

    const int bT   = b * T_;
    const int hoff = h * HD_;
    const int rw1  = warp * 16 + g;
    const int rw2  = rw1 + 8;

    const int lr = tid >> 2;
    const int lc = (tid & 3) * 4;

    const uint32_t* q1 = qkv + ((size_t)(bT + qt * AQ + rw1)) * (3 * D_) + hoff;
    const uint32_t* q2 = q1 + (size_t)8 * 3 * D_;
    uint32_t qa[8][4];
    #pragma unroll
    for (int ks = 0; ks < 8; ks++) {
        const int k = ks * 8;
        qa[ks][0] = __float_as_uint(0.125f * __uint_as_float(q1[k + t]));
        qa[ks][1] = __float_as_uint(0.125f * __uint_as_float(q2[k + t]));
        qa[ks][2] = __float_as_uint(0.125f * __uint_as_float(q1[k + t + 4]));
        qa[ks][3] = __float_as_uint(0.125f * __uint_as_float(q2[k + t + 4]));
    }

    float oa[8][4] = {};
    float m1 = -1e30f, m2 = -1e30f, l1 = 0.f, l2 = 0.f;

    const int ktmax = 2 * qt + 1;
    for (int kt = 0; kt <= ktmax; kt++) {
        const int k0 = kt * 64;
        {
            const uint32_t* base = qkv + ((size_t)(bT + k0 + lr)) * (3 * D_) + hoff;
            #pragma unroll
            for (int j = 0; j < 4; j++) {
                const int c = lc + j * 16;
                uint4 kv = *(const uint4*)(base + D_ + c);
                uint4 vv = *(const uint4*)(base + 2 * D_ + c);
                *(uint4*)&Ks[lr][c] = kv;
                VsT[c + 0][lr] = vv.x;
                VsT[c + 1][lr] = vv.y;
                VsT[c + 2][lr] = vv.z;
                VsT[c + 3][lr] = vv.w;
            }
        }
        __syncthreads();

        float sa[8][4] = {};
        #pragma unroll
        for (int ks = 0; ks < 8; ks++) {
            const int k = ks * 8;
            #pragma unroll
            for (int ni = 0; ni < 8; ni++) {
                uint32_t b0 = Ks[ni * 8 + g][k + t];
                uint32_t b1 = Ks[ni * 8 + g][k + t + 4];
                mma_tf32(sa[ni], qa[ks], b0, b1);
            }
        }

        if (kt >= 2 * qt) {
            const int off = (kt - 2 * qt) * 64;
            #pragma unroll
            for (int ni = 0; ni < 8; ni++) {
                const int c0 = off + ni * 8 + 2 * t, c1 = c0 + 1;
                if (c0 > rw1) sa[ni][0] = -1e30f;
                if (c1 > rw1) sa[ni][1] = -1e30f;
                if (c0 > rw2) sa[ni][2] = -1e30f;
                if (c1 > rw2) sa[ni][3] = -1e30f;
            }
        }

        float mx1 = -1e30f, mx2 = -1e30f;
        #pragma unroll
        for (int ni = 0; ni < 8; ni++) {
            mx1 = fmaxf(mx1, fmaxf(sa[ni][0], sa[ni][1]));
            mx2 = fmaxf(mx2, fmaxf(sa[ni][2], sa[ni][3]));
        }
        mx1 = fmaxf(mx1, __shfl_xor_sync(0xffffffffu, mx1, 1));
        mx1 = fmaxf(mx1, __shfl_xor_sync(0xffffffffu, mx1, 2));
        mx2 = fmaxf(mx2, __shfl_xor_sync(0xffffffffu, mx2, 1));
        mx2 = fmaxf(mx2, __shfl_xor_sync(0xffffffffu, mx2, 2));

        const float mn1 = fmaxf(m1, mx1);
        const float mn2 = fmaxf(m2, mx2);
        const float corr1 = __expf(m1 - mn1);
        const float corr2 = __expf(m2 - mn2);

        float rs1 = 0.f, rs2 = 0.f;
        #pragma unroll
        for (int ni = 0; ni < 8; ni++) {
            sa[ni][0] = __expf(sa[ni][0] - mn1);
            sa[ni][1] = __expf(sa[ni][1] - mn1);
            sa[ni][2] = __expf(sa[ni][2] - mn2);
            sa[ni][3] = __expf(sa[ni][3] - mn2);
            rs1 += sa[ni][0] + sa[ni][1];
            rs2 += sa[ni][2] + sa[ni][3];
        }
        rs1 += __shfl_xor_sync(0xffffffffu, rs1, 1);
        rs1 += __shfl_xor_sync(0xffffffffu, rs1, 2);
        rs2 += __shfl_xor_sync(0xffffffffu, rs2, 1);
        rs2 += __shfl_xor_sync(0xffffffffu, rs2, 2);
        l1 = l1 * corr1 + rs1;
        l2 = l2 * corr2 + rs2;
        m1 = mn1; m2 = mn2;

        #pragma unroll
        for (int ni = 0; ni < 8; ni++) {
            oa[ni][0] *= corr1; oa[ni][1] *= corr1;
            oa[ni][2] *= corr2; oa[ni][3] *= corr2;
        }

        const int L1 = g * 4 + (t >> 1);
        const int L2 = L1 + 2;
        const bool odd = (t & 1);
        #pragma unroll
        for (int ks = 0; ks < 8; ks++) {
            uint32_t p0 = f2tf(sa[ks][0]);
            uint32_t p1 = f2tf(sa[ks][1]);
            uint32_t p2 = f2tf(sa[ks][2]);
            uint32_t p3 = f2tf(sa[ks][3]);
            uint32_t v0 = __shfl_sync(0xffffffffu, p0, L1);
            uint32_t v1 = __shfl_sync(0xffffffffu, p1, L1);
            uint32_t v2 = __shfl_sync(0xffffffffu, p2, L1);
            uint32_t v3 = __shfl_sync(0xffffffffu, p3, L1);
            uint32_t w0 = __shfl_sync(0xffffffffu, p0, L2);
            uint32_t w1 = __shfl_sync(0xffffffffu, p1, L2);
            uint32_t w2 = __shfl_sync(0xffffffffu, p2, L2);
            uint32_t w3 = __shfl_sync(0xffffffffu, p3, L2);
            uint32_t pa[4];
            pa[0] = odd ? v1 : v0;
            pa[1] = odd ? v3 : v2;
            pa[2] = odd ? w1 : w0;
            pa[3] = odd ? w3 : w2;

            const int k = ks * 8;
            #pragma unroll
            for (int ni = 0; ni < 8; ni++) {
                uint32_t b0 = VsT[ni * 8 + g][k + t];
                uint32_t b1 = VsT[ni * 8 + g][k + t + 4];
                mma_tf32(oa[ni], pa, b0, b1);
            }
        }
        __syncthreads();
    }

    const float inv1 = 1.f / l1;
    const float inv2 = 1.f / l2;
    uint32_t* o1 = out + ((size_t)(bT + qt * AQ + rw1)) * D_ + hoff;
    uint32_t* o2 = o1 + (size_t)8 * D_;
    #pragma unroll
    for (int ni = 0; ni < 8; ni++) {
        const int c = ni * 8 + 2 * t;
        *(uint2*)(o1 + c) = make_uint2(f2tf(oa[ni][0] * inv1), f2tf(oa[ni][1] * inv1));
        *(uint2*)(o2 + c) = make_uint2(f2tf(oa[ni][2] * inv2), f2tf(oa[ni][3] * inv2));
    }
}

// ---------------------------------------------------------------------------
extern "C" void kernel_launch(void* const* d_in, const int* in_sizes, int n_in,
                              void* d_out, int out_size)
{
    (void)in_sizes; (void)n_in; (void)out_size;
    const float* x    = (const float*)d_in[0];   // [B,T,D]
    const float* Wqkv = (const float*)d_in[1];   // [3D, D]
    const float* Wout = (const float*)d_in[2];   // [D, D]
    float* out = (float*)d_out;                  // [B,T,D]

    uint32_t *x_tf, *wq_tf, *wo_tf, *qkv, *att;
    cudaGetSymbolAddress((void**)&x_tf,  g_x_tf);
    cudaGetSymbolAddress((void**)&wq_tf, g_wq_tf);
    cudaGetSymbolAddress((void**)&wo_tf, g_wo_tf);
    cudaGetSymbolAddress((void**)&qkv,   g_qkv);
    cudaGetSymbolAddress((void**)&att,   g_att);

    cudaFuncSetAttribute(gemm_tt32,
        cudaFuncAttributeMaxDynamicSharedMemorySize, GEMM_SMEM);

    // 0) pre-convert inputs to tf32 bits
    {
        const int nx = M_TOT * D_;
        const int nq = 3 * D_ * D_;
        const int no = D_ * D_;
        conv_tf32_kernel<<<nx / 1024, 256>>>(x, x_tf, nx);
        conv_tf32_kernel<<<nq / 1024, 256>>>(Wqkv, wq_tf, nq);
        conv_tf32_kernel<<<no / 1024, 256>>>(Wout, wo_tf, no);
    }
    // 1) qkv = x @ Wqkv^T : M=4096, N=3072, K=1024 (tf32 bits out)
    {
        dim3 grid(3 * D_ / GBN, M_TOT / GBM);     // 24 x 32
        gemm_tt32<<<grid, 128, GEMM_SMEM>>>(x_tf, wq_tf, qkv, M_TOT, 3 * D_, D_, 1);
    }
    // 2) causal flash attention -> att (tf32 bits)
    {
        dim3 grid(T_ / AQ, H_, B_);
        attn_tc_kernel<<<grid, 256>>>(qkv, att);
    }
    // 3) out = att @ Wout^T : M=4096, N=1024, K=1024 (fp32 out)
    {
        dim3 grid(D_ / GBN, M_TOT / GBM);         // 8 x 32
        gemm_tt32<<<grid, 128, GEMM_SMEM>>>(att, wo_tf, out, M_TOT, D_, D_, 0);
    }
}

// round 13
// speedup vs baseline: 1.2523x; 1.2523x over previous
#include <cuda_runtime.h>
#include <cuda_bf16.h>
#include <cstdint>

// Problem constants
#define B_   2
#define T_   2048
#define D_   1024
#define H_   16
#define HD_  64
#define M_TOT (B_ * T_)          // 4096 rows

// Scratch (alloc-free rule: __device__ globals). All tf32 bit patterns.
__device__ __align__(16) uint32_t g_x_tf [(size_t)M_TOT * D_];
__device__ __align__(16) uint32_t g_wq_tf[(size_t)3 * D_ * D_];
__device__ __align__(16) uint32_t g_wo_tf[(size_t)D_ * D_];
__device__ __align__(16) uint32_t g_qkv  [(size_t)M_TOT * 3 * D_];
__device__ __align__(16) uint32_t g_att  [(size_t)M_TOT * D_];

// ---------------------------------------------------------------------------
// helpers
// ---------------------------------------------------------------------------
__device__ __forceinline__ uint32_t f2tf(float x) {
    uint32_t u; asm("cvt.rna.tf32.f32 %0, %1;" : "=r"(u) : "f"(x)); return u;
}
__device__ __forceinline__ void mma_tf32(float* c, const uint32_t* a,
                                         uint32_t b0, uint32_t b1) {
    asm volatile(
        "mma.sync.aligned.m16n8k8.row.col.f32.tf32.tf32.f32 "
        "{%0,%1,%2,%3}, {%4,%5,%6,%7}, {%8,%9}, {%0,%1,%2,%3};\n"
        : "+f"(c[0]), "+f"(c[1]), "+f"(c[2]), "+f"(c[3])
        : "r"(a[0]), "r"(a[1]), "r"(a[2]), "r"(a[3]), "r"(b0), "r"(b1));
}

// ---------------------------------------------------------------------------
// elementwise fp32 -> tf32 bits
// ---------------------------------------------------------------------------
__global__ void __launch_bounds__(256) conv_tf32_kernel(
    const float* __restrict__ in, uint32_t* __restrict__ out, int n)
{
    int i = (blockIdx.x * 256 + threadIdx.x) * 4;
    if (i < n) {
        float4 v = *(const float4*)(in + i);
        uint4 o = make_uint4(f2tf(v.x), f2tf(v.y), f2tf(v.z), f2tf(v.w));
        *(uint4*)(out + i) = o;
    }
}

// ---------------------------------------------------------------------------
// TF32 mma.sync GEMM v4 — R5's measured-best shape (128x64 block, 4 warps,
// warp tile 64x32, BK=32, REGISTER staging) with two deltas:
//   (a) pre-converted tf32 inputs -> raw uint4 smem stores, zero CVT in loop
//   (b) double-buffered smem, ONE barrier per BK iteration:
//       iter kt: store regs->smem[(kt+1)&1]; load regs(kt+2); compute smem[kt&1]; bar
//       store(kt+1) overwrites the buffer last read by compute(kt-1), which the
//       end-of-iter barrier of kt-1 proved complete.
// Pitch 36: STS.128 phases hit 8 distinct 4-wide bank groups; fragment LDS
// (4g+t) mod 32 all distinct. conv_out: 1 -> tf32 bits out, 0 -> fp32 out.
// ---------------------------------------------------------------------------
#define GBM 128
#define GBN 64
#define GBK 32
#define GP  36                        // row pitch (words)
#define GAW (GBM * GP)                // A stage words = 4608
#define GSW (GAW + GBN * GP)          // stage words   = 6912
#define GEMM_SMEM (2 * GSW * 4)       // 55296 bytes

__device__ __forceinline__ void gemm_load_regs(
    const uint32_t* __restrict__ A, const uint32_t* __restrict__ W,
    int m0, int n0, int K, int kt, int tid, uint4* ra, uint4* rw)
{
    const int row = tid >> 3;            // 0..15
    const int c4  = tid & 7;             // uint4 column
    const uint32_t* gA = A + (size_t)(m0 + row) * K + kt * GBK + c4 * 4;
    #pragma unroll
    for (int e = 0; e < 8; e++) ra[e] = *(const uint4*)(gA + (size_t)(16 * e) * K);
    const uint32_t* gW = W + (size_t)(n0 + row) * K + kt * GBK + c4 * 4;
    #pragma unroll
    for (int e = 0; e < 4; e++) rw[e] = *(const uint4*)(gW + (size_t)(16 * e) * K);
}

__device__ __forceinline__ void gemm_store_stage(
    uint32_t* __restrict__ st, int tid, const uint4* ra, const uint4* rw)
{
    const int row = tid >> 3;
    const int c4  = tid & 7;
    #pragma unroll
    for (int e = 0; e < 8; e++)
        *(uint4*)&st[(row + 16 * e) * GP + c4 * 4] = ra[e];
    uint32_t* wb = st + GAW;
    #pragma unroll
    for (int e = 0; e < 4; e++)
        *(uint4*)&wb[(row + 16 * e) * GP + c4 * 4] = rw[e];
}

__global__ void __launch_bounds__(128) gemm_tt32(
    const uint32_t* __restrict__ A, const uint32_t* __restrict__ W,
    void* __restrict__ Cout, int M, int N, int K, int conv_out)
{
    extern __shared__ uint32_t dsm[];

    const int tid  = threadIdx.x;
    const int warp = tid >> 5;
    const int lane = tid & 31;
    const int g = lane >> 2;
    const int t = lane & 3;
    const int wm = (warp >> 1) * 64;     // 0, 64
    const int wn = (warp & 1) * 32;      // 0, 32

    const int m0 = blockIdx.y * GBM;
    const int n0 = blockIdx.x * GBN;

    float acc[4][4][4] = {};
    uint4 ra[8], rw[4];
    const int KT = K / GBK;              // 32

    // prologue
    gemm_load_regs(A, W, m0, n0, K, 0, tid, ra, rw);
    gemm_store_stage(dsm, tid, ra, rw);
    gemm_load_regs(A, W, m0, n0, K, 1, tid, ra, rw);
    __syncthreads();

    for (int kt = 0; kt < KT; kt++) {
        if (kt + 1 < KT)
            gemm_store_stage(dsm + ((kt + 1) & 1) * GSW, tid, ra, rw);
        if (kt + 2 < KT)
            gemm_load_regs(A, W, m0, n0, K, kt + 2, tid, ra, rw);

        const uint32_t* As = dsm + (kt & 1) * GSW;
        const uint32_t* Bs = As + GAW;
        #pragma unroll
        for (int ks = 0; ks < 4; ks++) {
            const int k = ks * 8;
            uint32_t af[4][4];
            #pragma unroll
            for (int mi = 0; mi < 4; mi++) {
                const int r = wm + mi * 16 + g;
                af[mi][0] = As[r * GP + k + t];
                af[mi][1] = As[(r + 8) * GP + k + t];
                af[mi][2] = As[r * GP + k + t + 4];
                af[mi][3] = As[(r + 8) * GP + k + t + 4];
            }
            #pragma unroll
            for (int ni = 0; ni < 4; ni++) {
                const int rb = wn + ni * 8 + g;
                uint32_t b0 = Bs[rb * GP + k + t];
                uint32_t b1 = Bs[rb * GP + k + t + 4];
                #pragma unroll
                for (int mi = 0; mi < 4; mi++)
                    mma_tf32(acc[mi][ni], af[mi], b0, b1);
            }
        }
        __syncthreads();
    }

    // epilogue
    if (conv_out) {
        uint32_t* C = (uint32_t*)Cout;
        #pragma unroll
        for (int mi = 0; mi < 4; mi++) {
            const int r1 = m0 + wm + mi * 16 + g;
            const int r2 = r1 + 8;
            #pragma unroll
            for (int ni = 0; ni < 4; ni++) {
                const int c = n0 + wn + ni * 8 + 2 * t;
                *(uint2*)&C[(size_t)r1 * N + c] =
                    make_uint2(f2tf(acc[mi][ni][0]), f2tf(acc[mi][ni][1]));
                *(uint2*)&C[(size_t)r2 * N + c] =
                    make_uint2(f2tf(acc[mi][ni][2]), f2tf(acc[mi][ni][3]));
            }
        }
    } else {
        float* C = (float*)Cout;
        #pragma unroll
        for (int mi = 0; mi < 4; mi++) {
            const int r1 = m0 + wm + mi * 16 + g;
            const int r2 = r1 + 8;
            #pragma unroll
            for (int ni = 0; ni < 4; ni++) {
                const int c = n0 + wn + ni * 8 + 2 * t;
                *(float2*)&C[(size_t)r1 * N + c] =
                    make_float2(acc[mi][ni][0], acc[mi][ni][1]);
                *(float2*)&C[(size_t)r2 * N + c] =
                    make_float2(acc[mi][ni][2], acc[mi][ni][3]);
            }
        }
    }
}

// ---------------------------------------------------------------------------
// Tensor-core flash attention (causal), tf32 inputs — R9 version (measured
// best, 223us). Grid: (T/128, H, B), 256 threads = 8 warps.
// ---------------------------------------------------------------------------
#define AQ 128

__global__ void __launch_bounds__(256) attn_tc_kernel(
    const uint32_t* __restrict__ qkv, uint32_t* __restrict__ out)
{
    __shared__ uint32_t Ks[64][68];
    __shared__ uint32_t VsT[64][68];

    const int qt  = gridDim.x - 1 - blockIdx.x;  // heavy first
    const int h   = blockIdx.y;
    const int b   = blockIdx.z;
    const int tid = threadIdx.x;
    const int warp = tid >> 5;
    const int lane = tid & 31;
    const int g = lane >> 2;
    const int t = lane & 3;

    const int bT   = b * T_;
    const int hoff = h * HD_;
    const int rw1  = warp * 16 + g;
    const int rw2  = rw1 + 8;

    const int lr = tid >> 2;
    const int lc = (tid & 3) * 4;

    const uint32_t* q1 = qkv + ((size_t)(bT + qt * AQ + rw1)) * (3 * D_) + hoff;
    const uint32_t* q2 = q1 + (size_t)8 * 3 * D_;
    uint32_t qa[8][4];
    #pragma unroll
    for (int ks = 0; ks < 8; ks++) {
        const int k = ks * 8;
        qa[ks][0] = __float_as_uint(0.125f * __uint_as_float(q1[k + t]));
        qa[ks][1] = __float_as_uint(0.125f * __uint_as_float(q2[k + t]));
        qa[ks][2] = __float_as_uint(0.125f * __uint_as_float(q1[k + t + 4]));
        qa[ks][3] = __float_as_uint(0.125f * __uint_as_float(q2[k + t + 4]));
    }

    float oa[8][4] = {};
    float m1 = -1e30f, m2 = -1e30f, l1 = 0.f, l2 = 0.f;

    const int ktmax = 2 * qt + 1;
    for (int kt = 0; kt <= ktmax; kt++) {
        const int k0 = kt * 64;
        {
            const uint32_t* base = qkv + ((size_t)(bT + k0 + lr)) * (3 * D_) + hoff;
            #pragma unroll
            for (int j = 0; j < 4; j++) {
                const int c = lc + j * 16;
                uint4 kv = *(const uint4*)(base + D_ + c);
                uint4 vv = *(const uint4*)(base + 2 * D_ + c);
                *(uint4*)&Ks[lr][c] = kv;
                VsT[c + 0][lr] = vv.x;
                VsT[c + 1][lr] = vv.y;
                VsT[c + 2][lr] = vv.z;
                VsT[c + 3][lr] = vv.w;
            }
        }
        __syncthreads();

        float sa[8][4] = {};
        #pragma unroll
        for (int ks = 0; ks < 8; ks++) {
            const int k = ks * 8;
            #pragma unroll
            for (int ni = 0; ni < 8; ni++) {
                uint32_t b0 = Ks[ni * 8 + g][k + t];
                uint32_t b1 = Ks[ni * 8 + g][k + t + 4];
                mma_tf32(sa[ni], qa[ks], b0, b1);
            }
        }

        if (kt >= 2 * qt) {
            const int off = (kt - 2 * qt) * 64;
            #pragma unroll
            for (int ni = 0; ni < 8; ni++) {
                const int c0 = off + ni * 8 + 2 * t, c1 = c0 + 1;
                if (c0 > rw1) sa[ni][0] = -1e30f;
                if (c1 > rw1) sa[ni][1] = -1e30f;
                if (c0 > rw2) sa[ni][2] = -1e30f;
                if (c1 > rw2) sa[ni][3] = -1e30f;
            }
        }

        float mx1 = -1e30f, mx2 = -1e30f;
        #pragma unroll
        for (int ni = 0; ni < 8; ni++) {
            mx1 = fmaxf(mx1, fmaxf(sa[ni][0], sa[ni][1]));
            mx2 = fmaxf(mx2, fmaxf(sa[ni][2], sa[ni][3]));
        }
        mx1 = fmaxf(mx1, __shfl_xor_sync(0xffffffffu, mx1, 1));
        mx1 = fmaxf(mx1, __shfl_xor_sync(0xffffffffu, mx1, 2));
        mx2 = fmaxf(mx2, __shfl_xor_sync(0xffffffffu, mx2, 1));
        mx2 = fmaxf(mx2, __shfl_xor_sync(0xffffffffu, mx2, 2));

        const float mn1 = fmaxf(m1, mx1);
        const float mn2 = fmaxf(m2, mx2);
        const float corr1 = __expf(m1 - mn1);
        const float corr2 = __expf(m2 - mn2);

        float rs1 = 0.f, rs2 = 0.f;
        #pragma unroll
        for (int ni = 0; ni < 8; ni++) {
            sa[ni][0] = __expf(sa[ni][0] - mn1);
            sa[ni][1] = __expf(sa[ni][1] - mn1);
            sa[ni][2] = __expf(sa[ni][2] - mn2);
            sa[ni][3] = __expf(sa[ni][3] - mn2);
            rs1 += sa[ni][0] + sa[ni][1];
            rs2 += sa[ni][2] + sa[ni][3];
        }
        rs1 += __shfl_xor_sync(0xffffffffu, rs1, 1);
        rs1 += __shfl_xor_sync(0xffffffffu, rs1, 2);
        rs2 += __shfl_xor_sync(0xffffffffu, rs2, 1);
        rs2 += __shfl_xor_sync(0xffffffffu, rs2, 2);
        l1 = l1 * corr1 + rs1;
        l2 = l2 * corr2 + rs2;
        m1 = mn1; m2 = mn2;

        #pragma unroll
        for (int ni = 0; ni < 8; ni++) {
            oa[ni][0] *= corr1; oa[ni][1] *= corr1;
            oa[ni][2] *= corr2; oa[ni][3] *= corr2;
        }

        const int L1 = g * 4 + (t >> 1);
        const int L2 = L1 + 2;
        const bool odd = (t & 1);
        #pragma unroll
        for (int ks = 0; ks < 8; ks++) {
            uint32_t p0 = f2tf(sa[ks][0]);
            uint32_t p1 = f2tf(sa[ks][1]);
            uint32_t p2 = f2tf(sa[ks][2]);
            uint32_t p3 = f2tf(sa[ks][3]);
            uint32_t v0 = __shfl_sync(0xffffffffu, p0, L1);
            uint32_t v1 = __shfl_sync(0xffffffffu, p1, L1);
            uint32_t v2 = __shfl_sync(0xffffffffu, p2, L1);
            uint32_t v3 = __shfl_sync(0xffffffffu, p3, L1);
            uint32_t w0 = __shfl_sync(0xffffffffu, p0, L2);
            uint32_t w1 = __shfl_sync(0xffffffffu, p1, L2);
            uint32_t w2 = __shfl_sync(0xffffffffu, p2, L2);
            uint32_t w3 = __shfl_sync(0xffffffffu, p3, L2);
            uint32_t pa[4];
            pa[0] = odd ? v1 : v0;
            pa[1] = odd ? v3 : v2;
            pa[2] = odd ? w1 : w0;
            pa[3] = odd ? w3 : w2;

            const int k = ks * 8;
            #pragma unroll
            for (int ni = 0; ni < 8; ni++) {
                uint32_t b0 = VsT[ni * 8 + g][k + t];
                uint32_t b1 = VsT[ni * 8 + g][k + t + 4];
                mma_tf32(oa[ni], pa, b0, b1);
            }
        }
        __syncthreads();
    }

    const float inv1 = 1.f / l1;
    const float inv2 = 1.f / l2;
    uint32_t* o1 = out + ((size_t)(bT + qt * AQ + rw1)) * D_ + hoff;
    uint32_t* o2 = o1 + (size_t)8 * D_;
    #pragma unroll
    for (int ni = 0; ni < 8; ni++) {
        const int c = ni * 8 + 2 * t;
        *(uint2*)(o1 + c) = make_uint2(f2tf(oa[ni][0] * inv1), f2tf(oa[ni][1] * inv1));
        *(uint2*)(o2 + c) = make_uint2(f2tf(oa[ni][2] * inv2), f2tf(oa[ni][3] * inv2));
    }
}

// ---------------------------------------------------------------------------
extern "C" void kernel_launch(void* const* d_in, const int* in_sizes, int n_in,
                              void* d_out, int out_size)
{
    (void)in_sizes; (void)n_in; (void)out_size;
    const float* x    = (const float*)d_in[0];   // [B,T,D]
    const float* Wqkv = (const float*)d_in[1];   // [3D, D]
    const float* Wout = (const float*)d_in[2];   // [D, D]
    float* out = (float*)d_out;                  // [B,T,D]

    uint32_t *x_tf, *wq_tf, *wo_tf, *qkv, *att;
    cudaGetSymbolAddress((void**)&x_tf,  g_x_tf);
    cudaGetSymbolAddress((void**)&wq_tf, g_wq_tf);
    cudaGetSymbolAddress((void**)&wo_tf, g_wo_tf);
    cudaGetSymbolAddress((void**)&qkv,   g_qkv);
    cudaGetSymbolAddress((void**)&att,   g_att);

    cudaFuncSetAttribute(gemm_tt32,
        cudaFuncAttributeMaxDynamicSharedMemorySize, GEMM_SMEM);

    // 0) pre-convert inputs to tf32 bits
    {
        const int nx = M_TOT * D_;
        const int nq = 3 * D_ * D_;
        const int no = D_ * D_;
        conv_tf32_kernel<<<nx / 1024, 256>>>(x, x_tf, nx);
        conv_tf32_kernel<<<nq / 1024, 256>>>(Wqkv, wq_tf, nq);
        conv_tf32_kernel<<<no / 1024, 256>>>(Wout, wo_tf, no);
    }
    // 1) qkv = x @ Wqkv^T : M=4096, N=3072, K=1024 (tf32 bits out)
    {
        dim3 grid(3 * D_ / GBN, M_TOT / GBM);     // 48 x 32
        gemm_tt32<<<grid, 128, GEMM_SMEM>>>(x_tf, wq_tf, qkv, M_TOT, 3 * D_, D_, 1);
    }
    // 2) causal flash attention -> att (tf32 bits)
    {
        dim3 grid(T_ / AQ, H_, B_);
        attn_tc_kernel<<<grid, 256>>>(qkv, att);
    }
    // 3) out = att @ Wout^T : M=4096, N=1024, K=1024 (fp32 out)
    {
        dim3 grid(D_ / GBN, M_TOT / GBM);         // 16 x 32
        gemm_tt32<<<grid, 128, GEMM_SMEM>>>(att, wo_tf, out, M_TOT, D_, D_, 0);
    }
}

// round 14
// speedup vs baseline: 1.2570x; 1.0038x over previous
#include <cuda_runtime.h>
#include <cuda_bf16.h>
#include <cstdint>

// Problem constants
#define B_   2
#define T_   2048
#define D_   1024
#define H_   16
#define HD_  64
#define M_TOT (B_ * T_)          // 4096 rows

// Scratch (alloc-free rule: __device__ globals). All tf32 bit patterns.
__device__ __align__(16) uint32_t g_x_tf [(size_t)M_TOT * D_];
__device__ __align__(16) uint32_t g_wq_tf[(size_t)3 * D_ * D_];
__device__ __align__(16) uint32_t g_wo_tf[(size_t)D_ * D_];
__device__ __align__(16) uint32_t g_qkv  [(size_t)M_TOT * 3 * D_];
__device__ __align__(16) uint32_t g_att  [(size_t)M_TOT * D_];

// ---------------------------------------------------------------------------
// helpers
// ---------------------------------------------------------------------------
__device__ __forceinline__ uint32_t f2tf(float x) {
    uint32_t u; asm("cvt.rna.tf32.f32 %0, %1;" : "=r"(u) : "f"(x)); return u;
}
__device__ __forceinline__ void mma_tf32(float* c, const uint32_t* a,
                                         uint32_t b0, uint32_t b1) {
    asm volatile(
        "mma.sync.aligned.m16n8k8.row.col.f32.tf32.tf32.f32 "
        "{%0,%1,%2,%3}, {%4,%5,%6,%7}, {%8,%9}, {%0,%1,%2,%3};\n"
        : "+f"(c[0]), "+f"(c[1]), "+f"(c[2]), "+f"(c[3])
        : "r"(a[0]), "r"(a[1]), "r"(a[2]), "r"(a[3]), "r"(b0), "r"(b1));
}

// ---------------------------------------------------------------------------
// elementwise fp32 -> tf32 bits
// ---------------------------------------------------------------------------
__global__ void __launch_bounds__(256) conv_tf32_kernel(
    const float* __restrict__ in, uint32_t* __restrict__ out, int n)
{
    int i = (blockIdx.x * 256 + threadIdx.x) * 4;
    if (i < n) {
        float4 v = *(const float4*)(in + i);
        uint4 o = make_uint4(f2tf(v.x), f2tf(v.y), f2tf(v.z), f2tf(v.w));
        *(uint4*)(out + i) = o;
    }
}

// ---------------------------------------------------------------------------
// TF32 mma.sync GEMM v4 — R5's measured-best shape (128x64 block, 4 warps,
// warp tile 64x32, BK=32, REGISTER staging) with two deltas:
//   (a) pre-converted tf32 inputs -> raw uint4 smem stores, zero CVT in loop
//   (b) double-buffered smem, ONE barrier per BK iteration:
//       iter kt: store regs->smem[(kt+1)&1]; load regs(kt+2); compute smem[kt&1]; bar
//       store(kt+1) overwrites the buffer last read by compute(kt-1), which the
//       end-of-iter barrier of kt-1 proved complete.
// Pitch 36: STS.128 phases hit 8 distinct 4-wide bank groups; fragment LDS
// (4g+t) mod 32 all distinct. conv_out: 1 -> tf32 bits out, 0 -> fp32 out.
// ---------------------------------------------------------------------------
#define GBM 128
#define GBN 64
#define GBK 32
#define GP  36                        // row pitch (words)
#define GAW (GBM * GP)                // A stage words = 4608
#define GSW (GAW + GBN * GP)          // stage words   = 6912
#define GEMM_SMEM (2 * GSW * 4)       // 55296 bytes

__device__ __forceinline__ void gemm_load_regs(
    const uint32_t* __restrict__ A, const uint32_t* __restrict__ W,
    int m0, int n0, int K, int kt, int tid, uint4* ra, uint4* rw)
{
    const int row = tid >> 3;            // 0..15
    const int c4  = tid & 7;             // uint4 column
    const uint32_t* gA = A + (size_t)(m0 + row) * K + kt * GBK + c4 * 4;
    #pragma unroll
    for (int e = 0; e < 8; e++) ra[e] = *(const uint4*)(gA + (size_t)(16 * e) * K);
    const uint32_t* gW = W + (size_t)(n0 + row) * K + kt * GBK + c4 * 4;
    #pragma unroll
    for (int e = 0; e < 4; e++) rw[e] = *(const uint4*)(gW + (size_t)(16 * e) * K);
}

__device__ __forceinline__ void gemm_store_stage(
    uint32_t* __restrict__ st, int tid, const uint4* ra, const uint4* rw)
{
    const int row = tid >> 3;
    const int c4  = tid & 7;
    #pragma unroll
    for (int e = 0; e < 8; e++)
        *(uint4*)&st[(row + 16 * e) * GP + c4 * 4] = ra[e];
    uint32_t* wb = st + GAW;
    #pragma unroll
    for (int e = 0; e < 4; e++)
        *(uint4*)&wb[(row + 16 * e) * GP + c4 * 4] = rw[e];
}

__global__ void __launch_bounds__(128) gemm_tt32(
    const uint32_t* __restrict__ A, const uint32_t* __restrict__ W,
    void* __restrict__ Cout, int M, int N, int K, int conv_out)
{
    extern __shared__ uint32_t dsm[];

    const int tid  = threadIdx.x;
    const int warp = tid >> 5;
    const int lane = tid & 31;
    const int g = lane >> 2;
    const int t = lane & 3;
    const int wm = (warp >> 1) * 64;     // 0, 64
    const int wn = (warp & 1) * 32;      // 0, 32

    const int m0 = blockIdx.y * GBM;
    const int n0 = blockIdx.x * GBN;

    float acc[4][4][4] = {};
    uint4 ra[8], rw[4];
    const int KT = K / GBK;              // 32

    // prologue
    gemm_load_regs(A, W, m0, n0, K, 0, tid, ra, rw);
    gemm_store_stage(dsm, tid, ra, rw);
    gemm_load_regs(A, W, m0, n0, K, 1, tid, ra, rw);
    __syncthreads();

    for (int kt = 0; kt < KT; kt++) {
        if (kt + 1 < KT)
            gemm_store_stage(dsm + ((kt + 1) & 1) * GSW, tid, ra, rw);
        if (kt + 2 < KT)
            gemm_load_regs(A, W, m0, n0, K, kt + 2, tid, ra, rw);

        const uint32_t* As = dsm + (kt & 1) * GSW;
        const uint32_t* Bs = As + GAW;
        #pragma unroll
        for (int ks = 0; ks < 4; ks++) {
            const int k = ks * 8;
            uint32_t af[4][4];
            #pragma unroll
            for (int mi = 0; mi < 4; mi++) {
                const int r = wm + mi * 16 + g;
                af[mi][0] = As[r * GP + k + t];
                af[mi][1] = As[(r + 8) * GP + k + t];
                af[mi][2] = As[r * GP + k + t + 4];
                af[mi][3] = As[(r + 8) * GP + k + t + 4];
            }
            #pragma unroll
            for (int ni = 0; ni < 4; ni++) {
                const int rb = wn + ni * 8 + g;
                uint32_t b0 = Bs[rb * GP + k + t];
                uint32_t b1 = Bs[rb * GP + k + t + 4];
                #pragma unroll
                for (int mi = 0; mi < 4; mi++)
                    mma_tf32(acc[mi][ni], af[mi], b0, b1);
            }
        }
        __syncthreads();
    }

    // epilogue
    if (conv_out) {
        uint32_t* C = (uint32_t*)Cout;
        #pragma unroll
        for (int mi = 0; mi < 4; mi++) {
            const int r1 = m0 + wm + mi * 16 + g;
            const int r2 = r1 + 8;
            #pragma unroll
            for (int ni = 0; ni < 4; ni++) {
                const int c = n0 + wn + ni * 8 + 2 * t;
                *(uint2*)&C[(size_t)r1 * N + c] =
                    make_uint2(f2tf(acc[mi][ni][0]), f2tf(acc[mi][ni][1]));
                *(uint2*)&C[(size_t)r2 * N + c] =
                    make_uint2(f2tf(acc[mi][ni][2]), f2tf(acc[mi][ni][3]));
            }
        }
    } else {
        float* C = (float*)Cout;
        #pragma unroll
        for (int mi = 0; mi < 4; mi++) {
            const int r1 = m0 + wm + mi * 16 + g;
            const int r2 = r1 + 8;
            #pragma unroll
            for (int ni = 0; ni < 4; ni++) {
                const int c = n0 + wn + ni * 8 + 2 * t;
                *(float2*)&C[(size_t)r1 * N + c] =
                    make_float2(acc[mi][ni][0], acc[mi][ni][1]);
                *(float2*)&C[(size_t)r2 * N + c] =
                    make_float2(acc[mi][ni][2], acc[mi][ni][3]);
            }
        }
    }
}

// ---------------------------------------------------------------------------
// Tensor-core flash attention (causal), tf32 inputs — R9 version (measured
// best, 223us). Grid: (T/128, H, B), 256 threads = 8 warps.
// ---------------------------------------------------------------------------
#define AQ 128

__global__ void __launch_bounds__(256) attn_tc_kernel(
    const uint32_t* __restrict__ qkv, uint32_t* __restrict__ out)
{
    __shared__ uint32_t Ks[64][68];
    __shared__ uint32_t VsT[64][68];

    const int qt  = gridDim.x - 1 - blockIdx.x;  // heavy first
    const int h   = blockIdx.y;
    const int b   = blockIdx.z;
    const int tid = threadIdx.x;
    const int warp = tid >> 5;
    const int lane = tid & 31;
    const int g = lane >> 2;
    const int t = lane & 3;

    const int bT   = b * T_;
    const int hoff = h * HD_;
    const int rw1  = warp * 16 + g;
    const int rw2  = rw1 + 8;

    const int lr = tid >> 2;
    const int lc = (tid & 3) * 4;

    const uint32_t* q1 = qkv + ((size_t)(bT + qt * AQ + rw1)) * (3 * D_) + hoff;
    const uint32_t* q2 = q1 + (size_t)8 * 3 * D_;
    uint32_t qa[8][4];
    #pragma unroll
    for (int ks = 0; ks < 8; ks++) {
        const int k = ks * 8;
        qa[ks][0] = __float_as_uint(0.125f * __uint_as_float(q1[k + t]));
        qa[ks][1] = __float_as_uint(0.125f * __uint_as_float(q2[k + t]));
        qa[ks][2] = __float_as_uint(0.125f * __uint_as_float(q1[k + t + 4]));
        qa[ks][3] = __float_as_uint(0.125f * __uint_as_float(q2[k + t + 4]));
    }

    float oa[8][4] = {};
    float m1 = -1e30f, m2 = -1e30f, l1 = 0.f, l2 = 0.f;

    const int ktmax = 2 * qt + 1;
    for (int kt = 0; kt <= ktmax; kt++) {
        const int k0 = kt * 64;
        {
            const uint32_t* base = qkv + ((size_t)(bT + k0 + lr)) * (3 * D_) + hoff;
            #pragma unroll
            for (int j = 0; j < 4; j++) {
                const int c = lc + j * 16;
                uint4 kv = *(const uint4*)(base + D_ + c);
                uint4 vv = *(const uint4*)(base + 2 * D_ + c);
                *(uint4*)&Ks[lr][c] = kv;
                VsT[c + 0][lr] = vv.x;
                VsT[c + 1][lr] = vv.y;
                VsT[c + 2][lr] = vv.z;
                VsT[c + 3][lr] = vv.w;
            }
        }
        __syncthreads();

        float sa[8][4] = {};
        #pragma unroll
        for (int ks = 0; ks < 8; ks++) {
            const int k = ks * 8;
            #pragma unroll
            for (int ni = 0; ni < 8; ni++) {
                uint32_t b0 = Ks[ni * 8 + g][k + t];
                uint32_t b1 = Ks[ni * 8 + g][k + t + 4];
                mma_tf32(sa[ni], qa[ks], b0, b1);
            }
        }

        if (kt >= 2 * qt) {
            const int off = (kt - 2 * qt) * 64;
            #pragma unroll
            for (int ni = 0; ni < 8; ni++) {
                const int c0 = off + ni * 8 + 2 * t, c1 = c0 + 1;
                if (c0 > rw1) sa[ni][0] = -1e30f;
                if (c1 > rw1) sa[ni][1] = -1e30f;
                if (c0 > rw2) sa[ni][2] = -1e30f;
                if (c1 > rw2) sa[ni][3] = -1e30f;
            }
        }

        float mx1 = -1e30f, mx2 = -1e30f;
        #pragma unroll
        for (int ni = 0; ni < 8; ni++) {
            mx1 = fmaxf(mx1, fmaxf(sa[ni][0], sa[ni][1]));
            mx2 = fmaxf(mx2, fmaxf(sa[ni][2], sa[ni][3]));
        }
        mx1 = fmaxf(mx1, __shfl_xor_sync(0xffffffffu, mx1, 1));
        mx1 = fmaxf(mx1, __shfl_xor_sync(0xffffffffu, mx1, 2));
        mx2 = fmaxf(mx2, __shfl_xor_sync(0xffffffffu, mx2, 1));
        mx2 = fmaxf(mx2, __shfl_xor_sync(0xffffffffu, mx2, 2));

        const float mn1 = fmaxf(m1, mx1);
        const float mn2 = fmaxf(m2, mx2);
        const float corr1 = __expf(m1 - mn1);
        const float corr2 = __expf(m2 - mn2);

        float rs1 = 0.f, rs2 = 0.f;
        #pragma unroll
        for (int ni = 0; ni < 8; ni++) {
            sa[ni][0] = __expf(sa[ni][0] - mn1);
            sa[ni][1] = __expf(sa[ni][1] - mn1);
            sa[ni][2] = __expf(sa[ni][2] - mn2);
            sa[ni][3] = __expf(sa[ni][3] - mn2);
            rs1 += sa[ni][0] + sa[ni][1];
            rs2 += sa[ni][2] + sa[ni][3];
        }
        rs1 += __shfl_xor_sync(0xffffffffu, rs1, 1);
        rs1 += __shfl_xor_sync(0xffffffffu, rs1, 2);
        rs2 += __shfl_xor_sync(0xffffffffu, rs2, 1);
        rs2 += __shfl_xor_sync(0xffffffffu, rs2, 2);
        l1 = l1 * corr1 + rs1;
        l2 = l2 * corr2 + rs2;
        m1 = mn1; m2 = mn2;

        #pragma unroll
        for (int ni = 0; ni < 8; ni++) {
            oa[ni][0] *= corr1; oa[ni][1] *= corr1;
            oa[ni][2] *= corr2; oa[ni][3] *= corr2;
        }

        const int L1 = g * 4 + (t >> 1);
        const int L2 = L1 + 2;
        const bool odd = (t & 1);
        #pragma unroll
        for (int ks = 0; ks < 8; ks++) {
            uint32_t p0 = f2tf(sa[ks][0]);
            uint32_t p1 = f2tf(sa[ks][1]);
            uint32_t p2 = f2tf(sa[ks][2]);
            uint32_t p3 = f2tf(sa[ks][3]);
            uint32_t v0 = __shfl_sync(0xffffffffu, p0, L1);
            uint32_t v1 = __shfl_sync(0xffffffffu, p1, L1);
            uint32_t v2 = __shfl_sync(0xffffffffu, p2, L1);
            uint32_t v3 = __shfl_sync(0xffffffffu, p3, L1);
            uint32_t w0 = __shfl_sync(0xffffffffu, p0, L2);
            uint32_t w1 = __shfl_sync(0xffffffffu, p1, L2);
            uint32_t w2 = __shfl_sync(0xffffffffu, p2, L2);
            uint32_t w3 = __shfl_sync(0xffffffffu, p3, L2);
            uint32_t pa[4];
            pa[0] = odd ? v1 : v0;
            pa[1] = odd ? v3 : v2;
            pa[2] = odd ? w1 : w0;
            pa[3] = odd ? w3 : w2;

            const int k = ks * 8;
            #pragma unroll
            for (int ni = 0; ni < 8; ni++) {
                uint32_t b0 = VsT[ni * 8 + g][k + t];
                uint32_t b1 = VsT[ni * 8 + g][k + t + 4];
                mma_tf32(oa[ni], pa, b0, b1);
            }
        }
        __syncthreads();
    }

    const float inv1 = 1.f / l1;
    const float inv2 = 1.f / l2;
    uint32_t* o1 = out + ((size_t)(bT + qt * AQ + rw1)) * D_ + hoff;
    uint32_t* o2 = o1 + (size_t)8 * D_;
    #pragma unroll
    for (int ni = 0; ni < 8; ni++) {
        const int c = ni * 8 + 2 * t;
        *(uint2*)(o1 + c) = make_uint2(f2tf(oa[ni][0] * inv1), f2tf(oa[ni][1] * inv1));
        *(uint2*)(o2 + c) = make_uint2(f2tf(oa[ni][2] * inv2), f2tf(oa[ni][3] * inv2));
    }
}

// ---------------------------------------------------------------------------
extern "C" void kernel_launch(void* const* d_in, const int* in_sizes, int n_in,
                              void* d_out, int out_size)
{
    (void)in_sizes; (void)n_in; (void)out_size;
    const float* x    = (const float*)d_in[0];   // [B,T,D]
    const float* Wqkv = (const float*)d_in[1];   // [3D, D]
    const float* Wout = (const float*)d_in[2];   // [D, D]
    float* out = (float*)d_out;                  // [B,T,D]

    uint32_t *x_tf, *wq_tf, *wo_tf, *qkv, *att;
    cudaGetSymbolAddress((void**)&x_tf,  g_x_tf);
    cudaGetSymbolAddress((void**)&wq_tf, g_wq_tf);
    cudaGetSymbolAddress((void**)&wo_tf, g_wo_tf);
    cudaGetSymbolAddress((void**)&qkv,   g_qkv);
    cudaGetSymbolAddress((void**)&att,   g_att);

    cudaFuncSetAttribute(gemm_tt32,
        cudaFuncAttributeMaxDynamicSharedMemorySize, GEMM_SMEM);

    // 0) pre-convert inputs to tf32 bits
    {
        const int nx = M_TOT * D_;
        const int nq = 3 * D_ * D_;
        const int no = D_ * D_;
        conv_tf32_kernel<<<nx / 1024, 256>>>(x, x_tf, nx);
        conv_tf32_kernel<<<nq / 1024, 256>>>(Wqkv, wq_tf, nq);
        conv_tf32_kernel<<<no / 1024, 256>>>(Wout, wo_tf, no);
    }
    // 1) qkv = x @ Wqkv^T : M=4096, N=3072, K=1024 (tf32 bits out)
    {
        dim3 grid(3 * D_ / GBN, M_TOT / GBM);     // 48 x 32
        gemm_tt32<<<grid, 128, GEMM_SMEM>>>(x_tf, wq_tf, qkv, M_TOT, 3 * D_, D_, 1);
    }
    // 2) causal flash attention -> att (tf32 bits)
    {
        dim3 grid(T_ / AQ, H_, B_);
        attn_tc_kernel<<<grid, 256>>>(qkv, att);
    }
    // 3) out = att @ Wout^T : M=4096, N=1024, K=1024 (fp32 out)
    {
        dim3 grid(D_ / GBN, M_TOT / GBM);         // 16 x 32
        gemm_tt32<<<grid, 128, GEMM_SMEM>>>(att, wo_tf, out, M_TOT, D_, D_, 0);
    }
}

// round 15
// speedup vs baseline: 1.2582x; 1.0010x over previous
#include <cuda_runtime.h>
#include <cuda_bf16.h>
#include <cstdint>

// Problem constants
#define B_   2
#define T_   2048
#define D_   1024
#define H_   16
#define HD_  64
#define M_TOT (B_ * T_)          // 4096 rows

// Scratch (alloc-free rule: __device__ globals). All tf32 bit patterns.
__device__ __align__(16) uint32_t g_x_tf [(size_t)M_TOT * D_];
__device__ __align__(16) uint32_t g_wq_tf[(size_t)3 * D_ * D_];
__device__ __align__(16) uint32_t g_wo_tf[(size_t)D_ * D_];
__device__ __align__(16) uint32_t g_qkv  [(size_t)M_TOT * 3 * D_];
__device__ __align__(16) uint32_t g_att  [(size_t)M_TOT * D_];

// ---------------------------------------------------------------------------
// helpers
// ---------------------------------------------------------------------------
__device__ __forceinline__ uint32_t f2tf(float x) {
    uint32_t u; asm("cvt.rna.tf32.f32 %0, %1;" : "=r"(u) : "f"(x)); return u;
}
__device__ __forceinline__ void mma_tf32(float* c, const uint32_t* a,
                                         uint32_t b0, uint32_t b1) {
    asm volatile(
        "mma.sync.aligned.m16n8k8.row.col.f32.tf32.tf32.f32 "
        "{%0,%1,%2,%3}, {%4,%5,%6,%7}, {%8,%9}, {%0,%1,%2,%3};\n"
        : "+f"(c[0]), "+f"(c[1]), "+f"(c[2]), "+f"(c[3])
        : "r"(a[0]), "r"(a[1]), "r"(a[2]), "r"(a[3]), "r"(b0), "r"(b1));
}

// ---------------------------------------------------------------------------
// elementwise fp32 -> tf32 bits
// ---------------------------------------------------------------------------
__global__ void __launch_bounds__(256) conv_tf32_kernel(
    const float* __restrict__ in, uint32_t* __restrict__ out, int n)
{
    int i = (blockIdx.x * 256 + threadIdx.x) * 4;
    if (i < n) {
        float4 v = *(const float4*)(in + i);
        uint4 o = make_uint4(f2tf(v.x), f2tf(v.y), f2tf(v.z), f2tf(v.w));
        *(uint4*)(out + i) = o;
    }
}

// ---------------------------------------------------------------------------
// TF32 mma.sync GEMM v4 — R5's measured-best shape (128x64 block, 4 warps,
// warp tile 64x32, BK=32, REGISTER staging) with two deltas:
//   (a) pre-converted tf32 inputs -> raw uint4 smem stores, zero CVT in loop
//   (b) double-buffered smem, ONE barrier per BK iteration:
//       iter kt: store regs->smem[(kt+1)&1]; load regs(kt+2); compute smem[kt&1]; bar
//       store(kt+1) overwrites the buffer last read by compute(kt-1), which the
//       end-of-iter barrier of kt-1 proved complete.
// Pitch 36: STS.128 phases hit 8 distinct 4-wide bank groups; fragment LDS
// (4g+t) mod 32 all distinct. conv_out: 1 -> tf32 bits out, 0 -> fp32 out.
// ---------------------------------------------------------------------------
#define GBM 128
#define GBN 64
#define GBK 32
#define GP  36                        // row pitch (words)
#define GAW (GBM * GP)                // A stage words = 4608
#define GSW (GAW + GBN * GP)          // stage words   = 6912
#define GEMM_SMEM (2 * GSW * 4)       // 55296 bytes

__device__ __forceinline__ void gemm_load_regs(
    const uint32_t* __restrict__ A, const uint32_t* __restrict__ W,
    int m0, int n0, int K, int kt, int tid, uint4* ra, uint4* rw)
{
    const int row = tid >> 3;            // 0..15
    const int c4  = tid & 7;             // uint4 column
    const uint32_t* gA = A + (size_t)(m0 + row) * K + kt * GBK + c4 * 4;
    #pragma unroll
    for (int e = 0; e < 8; e++) ra[e] = *(const uint4*)(gA + (size_t)(16 * e) * K);
    const uint32_t* gW = W + (size_t)(n0 + row) * K + kt * GBK + c4 * 4;
    #pragma unroll
    for (int e = 0; e < 4; e++) rw[e] = *(const uint4*)(gW + (size_t)(16 * e) * K);
}

__device__ __forceinline__ void gemm_store_stage(
    uint32_t* __restrict__ st, int tid, const uint4* ra, const uint4* rw)
{
    const int row = tid >> 3;
    const int c4  = tid & 7;
    #pragma unroll
    for (int e = 0; e < 8; e++)
        *(uint4*)&st[(row + 16 * e) * GP + c4 * 4] = ra[e];
    uint32_t* wb = st + GAW;
    #pragma unroll
    for (int e = 0; e < 4; e++)
        *(uint4*)&wb[(row + 16 * e) * GP + c4 * 4] = rw[e];
}

__global__ void __launch_bounds__(128) gemm_tt32(
    const uint32_t* __restrict__ A, const uint32_t* __restrict__ W,
    void* __restrict__ Cout, int M, int N, int K, int conv_out)
{
    extern __shared__ uint32_t dsm[];

    const int tid  = threadIdx.x;
    const int warp = tid >> 5;
    const int lane = tid & 31;
    const int g = lane >> 2;
    const int t = lane & 3;
    const int wm = (warp >> 1) * 64;     // 0, 64
    const int wn = (warp & 1) * 32;      // 0, 32

    const int m0 = blockIdx.y * GBM;
    const int n0 = blockIdx.x * GBN;

    float acc[4][4][4] = {};
    uint4 ra[8], rw[4];
    const int KT = K / GBK;              // 32

    // prologue
    gemm_load_regs(A, W, m0, n0, K, 0, tid, ra, rw);
    gemm_store_stage(dsm, tid, ra, rw);
    gemm_load_regs(A, W, m0, n0, K, 1, tid, ra, rw);
    __syncthreads();

    for (int kt = 0; kt < KT; kt++) {
        if (kt + 1 < KT)
            gemm_store_stage(dsm + ((kt + 1) & 1) * GSW, tid, ra, rw);
        if (kt + 2 < KT)
            gemm_load_regs(A, W, m0, n0, K, kt + 2, tid, ra, rw);

        const uint32_t* As = dsm + (kt & 1) * GSW;
        const uint32_t* Bs = As + GAW;
        #pragma unroll
        for (int ks = 0; ks < 4; ks++) {
            const int k = ks * 8;
            uint32_t af[4][4];
            #pragma unroll
            for (int mi = 0; mi < 4; mi++) {
                const int r = wm + mi * 16 + g;
                af[mi][0] = As[r * GP + k + t];
                af[mi][1] = As[(r + 8) * GP + k + t];
                af[mi][2] = As[r * GP + k + t + 4];
                af[mi][3] = As[(r + 8) * GP + k + t + 4];
            }
            #pragma unroll
            for (int ni = 0; ni < 4; ni++) {
                const int rb = wn + ni * 8 + g;
                uint32_t b0 = Bs[rb * GP + k + t];
                uint32_t b1 = Bs[rb * GP + k + t + 4];
                #pragma unroll
                for (int mi = 0; mi < 4; mi++)
                    mma_tf32(acc[mi][ni], af[mi], b0, b1);
            }
        }
        __syncthreads();
    }

    // epilogue
    if (conv_out) {
        uint32_t* C = (uint32_t*)Cout;
        #pragma unroll
        for (int mi = 0; mi < 4; mi++) {
            const int r1 = m0 + wm + mi * 16 + g;
            const int r2 = r1 + 8;
            #pragma unroll
            for (int ni = 0; ni < 4; ni++) {
                const int c = n0 + wn + ni * 8 + 2 * t;
                *(uint2*)&C[(size_t)r1 * N + c] =
                    make_uint2(f2tf(acc[mi][ni][0]), f2tf(acc[mi][ni][1]));
                *(uint2*)&C[(size_t)r2 * N + c] =
                    make_uint2(f2tf(acc[mi][ni][2]), f2tf(acc[mi][ni][3]));
            }
        }
    } else {
        float* C = (float*)Cout;
        #pragma unroll
        for (int mi = 0; mi < 4; mi++) {
            const int r1 = m0 + wm + mi * 16 + g;
            const int r2 = r1 + 8;
            #pragma unroll
            for (int ni = 0; ni < 4; ni++) {
                const int c = n0 + wn + ni * 8 + 2 * t;
                *(float2*)&C[(size_t)r1 * N + c] =
                    make_float2(acc[mi][ni][0], acc[mi][ni][1]);
                *(float2*)&C[(size_t)r2 * N + c] =
                    make_float2(acc[mi][ni][2], acc[mi][ni][3]);
            }
        }
    }
}

// ---------------------------------------------------------------------------
// Tensor-core flash attention (causal), tf32 inputs — R9 version (measured
// best, 223us). Grid: (T/128, H, B), 256 threads = 8 warps.
// ---------------------------------------------------------------------------
#define AQ 128

__global__ void __launch_bounds__(256) attn_tc_kernel(
    const uint32_t* __restrict__ qkv, uint32_t* __restrict__ out)
{
    __shared__ uint32_t Ks[64][68];
    __shared__ uint32_t VsT[64][68];

    const int qt  = gridDim.x - 1 - blockIdx.x;  // heavy first
    const int h   = blockIdx.y;
    const int b   = blockIdx.z;
    const int tid = threadIdx.x;
    const int warp = tid >> 5;
    const int lane = tid & 31;
    const int g = lane >> 2;
    const int t = lane & 3;

    const int bT   = b * T_;
    const int hoff = h * HD_;
    const int rw1  = warp * 16 + g;
    const int rw2  = rw1 + 8;

    const int lr = tid >> 2;
    const int lc = (tid & 3) * 4;

    const uint32_t* q1 = qkv + ((size_t)(bT + qt * AQ + rw1)) * (3 * D_) + hoff;
    const uint32_t* q2 = q1 + (size_t)8 * 3 * D_;
    uint32_t qa[8][4];
    #pragma unroll
    for (int ks = 0; ks < 8; ks++) {
        const int k = ks * 8;
        qa[ks][0] = __float_as_uint(0.125f * __uint_as_float(q1[k + t]));
        qa[ks][1] = __float_as_uint(0.125f * __uint_as_float(q2[k + t]));
        qa[ks][2] = __float_as_uint(0.125f * __uint_as_float(q1[k + t + 4]));
        qa[ks][3] = __float_as_uint(0.125f * __uint_as_float(q2[k + t + 4]));
    }

    float oa[8][4] = {};
    float m1 = -1e30f, m2 = -1e30f, l1 = 0.f, l2 = 0.f;

    const int ktmax = 2 * qt + 1;
    for (int kt = 0; kt <= ktmax; kt++) {
        const int k0 = kt * 64;
        {
            const uint32_t* base = qkv + ((size_t)(bT + k0 + lr)) * (3 * D_) + hoff;
            #pragma unroll
            for (int j = 0; j < 4; j++) {
                const int c = lc + j * 16;
                uint4 kv = *(const uint4*)(base + D_ + c);
                uint4 vv = *(const uint4*)(base + 2 * D_ + c);
                *(uint4*)&Ks[lr][c] = kv;
                VsT[c + 0][lr] = vv.x;
                VsT[c + 1][lr] = vv.y;
                VsT[c + 2][lr] = vv.z;
                VsT[c + 3][lr] = vv.w;
            }
        }
        __syncthreads();

        float sa[8][4] = {};
        #pragma unroll
        for (int ks = 0; ks < 8; ks++) {
            const int k = ks * 8;
            #pragma unroll
            for (int ni = 0; ni < 8; ni++) {
                uint32_t b0 = Ks[ni * 8 + g][k + t];
                uint32_t b1 = Ks[ni * 8 + g][k + t + 4];
                mma_tf32(sa[ni], qa[ks], b0, b1);
            }
        }

        if (kt >= 2 * qt) {
            const int off = (kt - 2 * qt) * 64;
            #pragma unroll
            for (int ni = 0; ni < 8; ni++) {
                const int c0 = off + ni * 8 + 2 * t, c1 = c0 + 1;
                if (c0 > rw1) sa[ni][0] = -1e30f;
                if (c1 > rw1) sa[ni][1] = -1e30f;
                if (c0 > rw2) sa[ni][2] = -1e30f;
                if (c1 > rw2) sa[ni][3] = -1e30f;
            }
        }

        float mx1 = -1e30f, mx2 = -1e30f;
        #pragma unroll
        for (int ni = 0; ni < 8; ni++) {
            mx1 = fmaxf(mx1, fmaxf(sa[ni][0], sa[ni][1]));
            mx2 = fmaxf(mx2, fmaxf(sa[ni][2], sa[ni][3]));
        }
        mx1 = fmaxf(mx1, __shfl_xor_sync(0xffffffffu, mx1, 1));
        mx1 = fmaxf(mx1, __shfl_xor_sync(0xffffffffu, mx1, 2));
        mx2 = fmaxf(mx2, __shfl_xor_sync(0xffffffffu, mx2, 1));
        mx2 = fmaxf(mx2, __shfl_xor_sync(0xffffffffu, mx2, 2));

        const float mn1 = fmaxf(m1, mx1);
        const float mn2 = fmaxf(m2, mx2);
        const float corr1 = __expf(m1 - mn1);
        const float corr2 = __expf(m2 - mn2);

        float rs1 = 0.f, rs2 = 0.f;
        #pragma unroll
        for (int ni = 0; ni < 8; ni++) {
            sa[ni][0] = __expf(sa[ni][0] - mn1);
            sa[ni][1] = __expf(sa[ni][1] - mn1);
            sa[ni][2] = __expf(sa[ni][2] - mn2);
            sa[ni][3] = __expf(sa[ni][3] - mn2);
            rs1 += sa[ni][0] + sa[ni][1];
            rs2 += sa[ni][2] + sa[ni][3];
        }
        rs1 += __shfl_xor_sync(0xffffffffu, rs1, 1);
        rs1 += __shfl_xor_sync(0xffffffffu, rs1, 2);
        rs2 += __shfl_xor_sync(0xffffffffu, rs2, 1);
        rs2 += __shfl_xor_sync(0xffffffffu, rs2, 2);
        l1 = l1 * corr1 + rs1;
        l2 = l2 * corr2 + rs2;
        m1 = mn1; m2 = mn2;

        #pragma unroll
        for (int ni = 0; ni < 8; ni++) {
            oa[ni][0] *= corr1; oa[ni][1] *= corr1;
            oa[ni][2] *= corr2; oa[ni][3] *= corr2;
        }

        const int L1 = g * 4 + (t >> 1);
        const int L2 = L1 + 2;
        const bool odd = (t & 1);
        #pragma unroll
        for (int ks = 0; ks < 8; ks++) {
            uint32_t p0 = f2tf(sa[ks][0]);
            uint32_t p1 = f2tf(sa[ks][1]);
            uint32_t p2 = f2tf(sa[ks][2]);
            uint32_t p3 = f2tf(sa[ks][3]);
            uint32_t v0 = __shfl_sync(0xffffffffu, p0, L1);
            uint32_t v1 = __shfl_sync(0xffffffffu, p1, L1);
            uint32_t v2 = __shfl_sync(0xffffffffu, p2, L1);
            uint32_t v3 = __shfl_sync(0xffffffffu, p3, L1);
            uint32_t w0 = __shfl_sync(0xffffffffu, p0, L2);
            uint32_t w1 = __shfl_sync(0xffffffffu, p1, L2);
            uint32_t w2 = __shfl_sync(0xffffffffu, p2, L2);
            uint32_t w3 = __shfl_sync(0xffffffffu, p3, L2);
            uint32_t pa[4];
            pa[0] = odd ? v1 : v0;
            pa[1] = odd ? v3 : v2;
            pa[2] = odd ? w1 : w0;
            pa[3] = odd ? w3 : w2;

            const int k = ks * 8;
            #pragma unroll
            for (int ni = 0; ni < 8; ni++) {
                uint32_t b0 = VsT[ni * 8 + g][k + t];
                uint32_t b1 = VsT[ni * 8 + g][k + t + 4];
                mma_tf32(oa[ni], pa, b0, b1);
            }
        }
        __syncthreads();
    }

    const float inv1 = 1.f / l1;
    const float inv2 = 1.f / l2;
    uint32_t* o1 = out + ((size_t)(bT + qt * AQ + rw1)) * D_ + hoff;
    uint32_t* o2 = o1 + (size_t)8 * D_;
    #pragma unroll
    for (int ni = 0; ni < 8; ni++) {
        const int c = ni * 8 + 2 * t;
        *(uint2*)(o1 + c) = make_uint2(f2tf(oa[ni][0] * inv1), f2tf(oa[ni][1] * inv1));
        *(uint2*)(o2 + c) = make_uint2(f2tf(oa[ni][2] * inv2), f2tf(oa[ni][3] * inv2));
    }
}

// ---------------------------------------------------------------------------
extern "C" void kernel_launch(void* const* d_in, const int* in_sizes, int n_in,
                              void* d_out, int out_size)
{
    (void)in_sizes; (void)n_in; (void)out_size;
    const float* x    = (const float*)d_in[0];   // [B,T,D]
    const float* Wqkv = (const float*)d_in[1];   // [3D, D]
    const float* Wout = (const float*)d_in[2];   // [D, D]
    float* out = (float*)d_out;                  // [B,T,D]

    uint32_t *x_tf, *wq_tf, *wo_tf, *qkv, *att;
    cudaGetSymbolAddress((void**)&x_tf,  g_x_tf);
    cudaGetSymbolAddress((void**)&wq_tf, g_wq_tf);
    cudaGetSymbolAddress((void**)&wo_tf, g_wo_tf);
    cudaGetSymbolAddress((void**)&qkv,   g_qkv);
    cudaGetSymbolAddress((void**)&att,   g_att);

    cudaFuncSetAttribute(gemm_tt32,
        cudaFuncAttributeMaxDynamicSharedMemorySize, GEMM_SMEM);

    // 0) pre-convert inputs to tf32 bits
    {
        const int nx = M_TOT * D_;
        const int nq = 3 * D_ * D_;
        const int no = D_ * D_;
        conv_tf32_kernel<<<nx / 1024, 256>>>(x, x_tf, nx);
        conv_tf32_kernel<<<nq / 1024, 256>>>(Wqkv, wq_tf, nq);
        conv_tf32_kernel<<<no / 1024, 256>>>(Wout, wo_tf, no);
    }
    // 1) qkv = x @ Wqkv^T : M=4096, N=3072, K=1024 (tf32 bits out)
    {
        dim3 grid(3 * D_ / GBN, M_TOT / GBM);     // 48 x 32
        gemm_tt32<<<grid, 128, GEMM_SMEM>>>(x_tf, wq_tf, qkv, M_TOT, 3 * D_, D_, 1);
    }
    // 2) causal flash attention -> att (tf32 bits)
    {
        dim3 grid(T_ / AQ, H_, B_);
        attn_tc_kernel<<<grid, 256>>>(qkv, att);
    }
    // 3) out = att @ Wout^T : M=4096, N=1024, K=1024 (fp32 out)
    {
        dim3 grid(D_ / GBN, M_TOT / GBM);         // 16 x 32
        gemm_tt32<<<grid, 128, GEMM_SMEM>>>(att, wo_tf, out, M_TOT, D_, D_, 0);
    }
}